// round 15
// baseline (speedup 1.0000x reference)
#include <cuda_runtime.h>
#include <cstdint>

#define N_NODES 48
#define N_EDGES 192
#define DIM     1024
#define NN      (N_NODES * N_NODES)   // 2304
#define EE      (N_EDGES * N_EDGES)   // 36864
#define OUT_DIM NN                    // 2304
#define SPLITK  32
#define KC      (DIM / SPLITK)        // 32
#define N4      ((OUT_DIM * OUT_DIM) / 4)   // 1,327,104 float4
#define GEMM_BLOCKS (9 * SPLITK)      // 288
#define MP_BLOCKS   96
#define MAIN_BLOCKS (GEMM_BLOCKS + MP_BLOCKS)  // 384
#define PRE_BLOCKS  256               // 8 coeff rows each
#define PRE_THREADS 256

// Scratch (no cudaMalloc allowed)
__device__ float g_cn[DIM];
__device__ float g_ce[DIM];
__device__ float g_Mp[NN];
__device__ float g_MePart[SPLITK][EE];   // 4.7 MB, L2-resident

__device__ __forceinline__ float softplus_act(float x) {
    // relu(softplus(x) - 0.5)
    float sp = (x > 20.f) ? x : log1pf(expf(x));
    float v = sp - 0.5f;
    return v > 0.f ? v : 0.f;
}

// ---------------------------------------------------------------------------
// Kernel 1: coeff = tanh(W @ gw + b). 256 blocks x 256 thr, 8 rows per
// block -> 8 INDEPENDENT LDG.128 per thread (8.4MB demanded in flight
// chip-wide at once). The full 21MB zero-fill is issued between load issue
// and load consumption, hiding the STG cost inside the DRAM latency window.
// ---------------------------------------------------------------------------
__global__ void __launch_bounds__(PRE_THREADS)
k_pre(const float* __restrict__ Wn, const float* __restrict__ bn,
      const float* __restrict__ We, const float* __restrict__ be,
      const float* __restrict__ gw, float4* __restrict__ out4) {
    __shared__ float sred[64];              // 8 rows x 8 warps
    int t = threadIdx.x;
    int lane = t & 31, warp = t >> 5;
    int r0 = blockIdx.x * 8;                // 0..2040, never straddles Wn/We
    const float* W;
    const float* bias;
    float* outp;
    int rr;
    if (r0 < DIM) { W = Wn; bias = bn; outp = g_cn; rr = r0; }
    else          { W = We; bias = be; outp = g_ce; rr = r0 - DIM; }

    // 8 independent row loads (column t of each row)
    const float4* base = (const float4*)(W + (size_t)rr * DIM);
    float4 w0 = base[0 * 256 + t];
    float4 w1 = base[1 * 256 + t];
    float4 w2 = base[2 * 256 + t];
    float4 w3 = base[3 * 256 + t];
    float4 w4 = base[4 * 256 + t];
    float4 w5 = base[5 * 256 + t];
    float4 w6 = base[6 * 256 + t];
    float4 w7 = base[7 * 256 + t];
    float4 g  = ((const float4*)gw)[t];

    // zero-fill output while the 8 loads are in flight
    {
        float4 z = make_float4(0.f, 0.f, 0.f, 0.f);
        for (int i = blockIdx.x * PRE_THREADS + t; i < N4;
             i += PRE_BLOCKS * PRE_THREADS)
            out4[i] = z;
    }

    float s[8];
    s[0] = w0.x * g.x + w0.y * g.y + w0.z * g.z + w0.w * g.w;
    s[1] = w1.x * g.x + w1.y * g.y + w1.z * g.z + w1.w * g.w;
    s[2] = w2.x * g.x + w2.y * g.y + w2.z * g.z + w2.w * g.w;
    s[3] = w3.x * g.x + w3.y * g.y + w3.z * g.z + w3.w * g.w;
    s[4] = w4.x * g.x + w4.y * g.y + w4.z * g.z + w4.w * g.w;
    s[5] = w5.x * g.x + w5.y * g.y + w5.z * g.z + w5.w * g.w;
    s[6] = w6.x * g.x + w6.y * g.y + w6.z * g.z + w6.w * g.w;
    s[7] = w7.x * g.x + w7.y * g.y + w7.z * g.z + w7.w * g.w;
#pragma unroll
    for (int o = 16; o; o >>= 1)
#pragma unroll
        for (int i = 0; i < 8; i++)
            s[i] += __shfl_xor_sync(0xffffffffu, s[i], o);
    if (lane == 0) {
#pragma unroll
        for (int i = 0; i < 8; i++) sred[i * 8 + warp] = s[i];
    }
    __syncthreads();
    if (t < 8) {
        float acc = 0.f;
#pragma unroll
        for (int j = 0; j < 8; j++) acc += sred[t * 8 + j];
        outp[rr + t] = tanhf(acc + bias[rr + t]);
    }
}

// ---------------------------------------------------------------------------
// Kernel 2: blocks 0..287  -> Me split-K(32) GEMM partials, 64x64 tile,
//           k-major smem, contiguous 4x4 C tile per thread, both K-stages'
//           global operands prefetched before the first smem store.
//           blocks 288..383 -> Mp (48x48) into g_Mp scratch.
// ---------------------------------------------------------------------------
__global__ void __launch_bounds__(256, 2)
k_main(const float* __restrict__ ef1, const float* __restrict__ ef2,
       const float* __restrict__ x1, const float* __restrict__ x2) {
    int t = threadIdx.x;
    int b = blockIdx.x;

    if (b < GEMM_BLOCKS) {
        // ---- Me GEMM partial: C[m,n] = sum_k ef1[m,k]*ce[k]*ef2[n,k]
        __shared__ float4 As[16][17];   // [kk][rowgroup]
        __shared__ float4 Bs[16][17];
        float* Asf = (float*)As;        // row stride 68 floats
        float* Bsf = (float*)Bs;

        int tx = t & 15, ty = t >> 4;
        int bx = b % 3;
        int by = (b / 3) % 3;
        int kz = b / 9;                 // 0..31
        int lr = t >> 2;                // 0..63 (tile row this thread loads)
        int lc = (t & 3) * 4;           // 0,4,8,12 (k-chunk base)
        int k0 = kz * KC;
        const float* Arow = ef1 + (by * 64 + lr) * DIM;
        const float* Brow = ef2 + (bx * 64 + lr) * DIM;

        // prefetch both stages (6 independent LDG.128)
        float4 pa[2], pb[2], pc[2];
#pragma unroll
        for (int s = 0; s < 2; s++) {
            int kb = k0 + s * 16 + lc;
            pc[s] = *(const float4*)(g_ce + kb);
            pa[s] = *(const float4*)(Arow + kb);
            pb[s] = *(const float4*)(Brow + kb);
        }

        float acc[4][4] = {};
#pragma unroll
        for (int s = 0; s < 2; s++) {
            float4 a4 = pa[s], b4 = pb[s], c4 = pc[s];
            a4.x *= c4.x; a4.y *= c4.y; a4.z *= c4.z; a4.w *= c4.w;
            if (s) __syncthreads();
            Asf[(lc + 0) * 68 + lr] = a4.x;
            Asf[(lc + 1) * 68 + lr] = a4.y;
            Asf[(lc + 2) * 68 + lr] = a4.z;
            Asf[(lc + 3) * 68 + lr] = a4.w;
            Bsf[(lc + 0) * 68 + lr] = b4.x;
            Bsf[(lc + 1) * 68 + lr] = b4.y;
            Bsf[(lc + 2) * 68 + lr] = b4.z;
            Bsf[(lc + 3) * 68 + lr] = b4.w;
            __syncthreads();
#pragma unroll
            for (int kk = 0; kk < 16; kk++) {
                float4 av = As[kk][ty];
                float4 bv = Bs[kk][tx];
                float a[4] = {av.x, av.y, av.z, av.w};
                float bb[4] = {bv.x, bv.y, bv.z, bv.w};
#pragma unroll
                for (int j = 0; j < 4; j++)
#pragma unroll
                    for (int i = 0; i < 4; i++)
                        acc[j][i] += a[j] * bb[i];
            }
        }

        float* outp = g_MePart[kz];
#pragma unroll
        for (int j = 0; j < 4; j++) {
            int m = by * 64 + 4 * ty + j;
            int n = bx * 64 + 4 * tx;
            *(float4*)(outp + m * N_EDGES + n) =
                make_float4(acc[j][0], acc[j][1], acc[j][2], acc[j][3]);
        }
    } else {
        // ---- Mp: 768 warps, 3 outputs per warp, into g_Mp scratch.
        int lane = t & 31, warp = t >> 5;
        int w = (b - GEMM_BLOCKS) * 8 + warp;   // 0..767
        int idx0 = w * 3;
        int m = idx0 / N_NODES, n0 = idx0 % N_NODES;  // same m across the 3
        const float4* A  = (const float4*)(x1 + m * DIM);
        const float4* B0 = (const float4*)(x2 + n0 * DIM);
        const float4* C  = (const float4*)g_cn;
        float s0 = 0.f, s1 = 0.f, s2 = 0.f;
#pragma unroll
        for (int i = 0; i < 8; i++) {
            int k = i * 32 + lane;
            float4 a = A[k], c = C[k];
            a.x *= c.x; a.y *= c.y; a.z *= c.z; a.w *= c.w;
            float4 b0 = B0[k], b1 = B0[256 + k], b2 = B0[512 + k];
            s0 += a.x * b0.x + a.y * b0.y + a.z * b0.z + a.w * b0.w;
            s1 += a.x * b1.x + a.y * b1.y + a.z * b1.z + a.w * b1.w;
            s2 += a.x * b2.x + a.y * b2.y + a.z * b2.z + a.w * b2.w;
        }
#pragma unroll
        for (int o = 16; o; o >>= 1) {
            s0 += __shfl_xor_sync(0xffffffffu, s0, o);
            s1 += __shfl_xor_sync(0xffffffffu, s1, o);
            s2 += __shfl_xor_sync(0xffffffffu, s2, o);
        }
        if (lane == 0) {
            g_Mp[idx0 + 0] = softplus_act(s0);
            g_Mp[idx0 + 1] = softplus_act(s1);
            g_Mp[idx0 + 2] = softplus_act(s2);
        }
    }
}

// ---------------------------------------------------------------------------
// Kernel 3: 4 outputs per thread; 32 independent LDG.128 partial loads,
// activate, scatter-add edges into M; then the diagonal from g_Mp.
// value for pair (j1,j2) is Me.flat[j2*192+j1]:
//   M[head2[j2]*48+head1[j1], tail2[j2]*48+tail1[j1]] += act(.)
// ---------------------------------------------------------------------------
__global__ void __launch_bounds__(128)
k_scatter(const int* __restrict__ ei1, const int* __restrict__ ei2,
          float* __restrict__ M) {
    int i = blockIdx.x * 128 + threadIdx.x;
    if (i < EE / 4) {
        int idx = i * 4;
        float4 sv = make_float4(0.f, 0.f, 0.f, 0.f);
#pragma unroll
        for (int z = 0; z < SPLITK; z++) {
            float4 p = *(const float4*)(g_MePart[z] + idx);
            sv.x += p.x; sv.y += p.y; sv.z += p.z; sv.w += p.w;
        }
        int j2 = idx / N_EDGES;           // same row for all 4 (192 % 4 == 0)
        int n0 = idx % N_EDGES;
        int rb = ei2[j2] * N_NODES;                 // head2*48
        int cb = ei2[N_EDGES + j2] * N_NODES;       // tail2*48
        float v0 = softplus_act(sv.x);
        float v1 = softplus_act(sv.y);
        float v2 = softplus_act(sv.z);
        float v3 = softplus_act(sv.w);
        if (v0 > 0.f)
            atomicAdd(M + (size_t)(rb + ei1[n0 + 0]) * OUT_DIM
                        + cb + ei1[N_EDGES + n0 + 0], v0);
        if (v1 > 0.f)
            atomicAdd(M + (size_t)(rb + ei1[n0 + 1]) * OUT_DIM
                        + cb + ei1[N_EDGES + n0 + 1], v1);
        if (v2 > 0.f)
            atomicAdd(M + (size_t)(rb + ei1[n0 + 2]) * OUT_DIM
                        + cb + ei1[N_EDGES + n0 + 2], v2);
        if (v3 > 0.f)
            atomicAdd(M + (size_t)(rb + ei1[n0 + 3]) * OUT_DIM
                        + cb + ei1[N_EDGES + n0 + 3], v3);
    } else if (i < EE / 4 + NN / 4) {
        int a0 = (i - EE / 4) * 4;
        float4 d = *(const float4*)(g_Mp + a0);
        atomicAdd(M + (size_t)(a0 + 0) * (OUT_DIM + 1), d.x);
        atomicAdd(M + (size_t)(a0 + 1) * (OUT_DIM + 1), d.y);
        atomicAdd(M + (size_t)(a0 + 2) * (OUT_DIM + 1), d.z);
        atomicAdd(M + (size_t)(a0 + 3) * (OUT_DIM + 1), d.w);
    }
}

extern "C" void kernel_launch(void* const* d_in, const int* in_sizes, int n_in,
                              void* d_out, int out_size) {
    const float* x1  = (const float*)d_in[0];
    const float* x2  = (const float*)d_in[1];
    const float* ef1 = (const float*)d_in[2];
    const float* ef2 = (const float*)d_in[3];
    const float* gw  = (const float*)d_in[4];
    const float* Wn  = (const float*)d_in[5];
    const float* bn  = (const float*)d_in[6];
    const float* We  = (const float*)d_in[7];
    const float* be  = (const float*)d_in[8];
    const int*   ei1 = (const int*)d_in[9];
    const int*   ei2 = (const int*)d_in[10];
    float* M = (float*)d_out;

    k_pre<<<PRE_BLOCKS, PRE_THREADS>>>(Wn, bn, We, be, gw, (float4*)M);
    k_main<<<MAIN_BLOCKS, 256>>>(ef1, ef2, x1, x2);
    int sc_threads = EE / 4 + NN / 4;               // 9792
    k_scatter<<<(sc_threads + 127) / 128, 128>>>(ei1, ei2, M);
}